// round 8
// baseline (speedup 1.0000x reference)
#include <cuda_runtime.h>
#include <cstdint>
#include <math.h>

#define BB   16
#define CC   256
#define NN   16384
#define KK   64
#define TEMPF 20.0f
#define EPSF  1e-6f
#define EM_STEPS 3
#define NSPLIT 32
#define NBLK1 (NN/256)      // 64 GEMM1 n-blocks

typedef unsigned long long ull;

// -------- scratch (no allocations allowed -> device globals) --------
__device__ float g_m   [BB*CC*KK];                 // prototypes m [B][C][K]
__device__ float g_mtmp[BB*CC*KK];
__device__ float g_S   [BB*KK];
__device__ float g_Spart[NBLK1*BB*KK];
__device__ float g_part[(size_t)BB*NSPLIT*CC*KK];

__device__ __forceinline__ ull fma2(ull a, ull b, ull c) {
    ull d;
    asm("fma.rn.f32x2 %0, %1, %2, %3;" : "=l"(d) : "l"(a), "l"(b), "l"(c));
    return d;
}
__device__ __forceinline__ ull dup2(float v) {
    uint32_t u = __float_as_uint(v);
    return (ull)u | ((ull)u << 32);
}
__device__ __forceinline__ float lo32(ull v) { return __uint_as_float((uint32_t)v); }
__device__ __forceinline__ float hi32(ull v) { return __uint_as_float((uint32_t)(v >> 32)); }

// dup-layout offset for broadcast operand: k -> (k&7)*8 + (k>>3); lane kt reads [j*8 + kt]
__device__ __forceinline__ int koff(int k) { return (k & 7) * 8 + (k >> 3); }

// -------- init: broadcast mu to all batches --------
__global__ void k_init(const float* __restrict__ mu) {
    int idx = blockIdx.x * 256 + threadIdx.x;      // B*C*K
    g_m[idx] = mu[idx & (CC * KK - 1)];
}

// ---- GEMM1: z[b,n,k] = softmax_k( scale * sum_c x[b,c,n]*m[b,c,k] ), fused colsums
// grid (NN/256, BB), 256 threads. Tile 256n x 64k, per-thread 8n x 8k (n-paired f32x2).
template<bool TEMP_ON>
__global__ void __launch_bounds__(256)
k_gemm1(const float* __restrict__ x, float* __restrict__ z) {
    __shared__ __align__(16) float4 xs4[16][64];   // [c][n/4] : 16 x 256 floats (16KB)
    __shared__ ull msd[16 * 64];                   // dup b: [c][(k&7)*8+(k>>3)] (8KB)

    const int b  = blockIdx.y;
    const int n0 = blockIdx.x * 256;
    const int tid = threadIdx.x;
    const int kt = tid & 7;          // k = kt*8 .. kt*8+7
    const int nt = tid >> 3;         // n = nt*8 .. nt*8+7

    const float* __restrict__ xb = x   + (size_t)b * CC * NN;
    const float* __restrict__ mb = g_m + b * CC * KK;

    ull acc2[4][8];                  // [n-pair][k] ; halves = (n even, n odd)
#pragma unroll
    for (int i = 0; i < 4; i++)
#pragma unroll
        for (int j = 0; j < 8; j++) acc2[i][j] = 0ull;

    for (int cc = 0; cc < CC; cc += 16) {
#pragma unroll
        for (int it = 0; it < 4; it++) {           // x tile: 16c x 256n
            int idx = it * 256 + tid, r = idx >> 6, q = idx & 63;
            xs4[r][q] = *(const float4*)(xb + (size_t)(cc + r) * NN + n0 + q * 4);
        }
        {                                          // m tile: 16c x 64k, duplicated
            int r = tid >> 4, q = (tid & 15) * 4;
            float4 v = *(const float4*)(mb + (cc + r) * KK + q);
            float f[4] = {v.x, v.y, v.z, v.w};
#pragma unroll
            for (int e = 0; e < 4; e++) msd[r * 64 + koff(q + e)] = dup2(f[e]);
        }
        __syncthreads();

#pragma unroll
        for (int c = 0; c < 16; c++) {
            const ulonglong2* xr = (const ulonglong2*)(&xs4[c][0]);
            ulonglong2 A0 = xr[nt * 2], A1 = xr[nt * 2 + 1];
            ull a2[4] = {A0.x, A0.y, A1.x, A1.y};
            const ull* br = &msd[c * 64 + kt];
#pragma unroll
            for (int j = 0; j < 8; j++) {
                ull bd = br[j * 8];
#pragma unroll
                for (int i = 0; i < 4; i++) acc2[i][j] = fma2(a2[i], bd, acc2[i][j]);
            }
        }
        __syncthreads();
    }

    // fused softmax over k: each (n-row) spread over 8 kt lanes x 8 values
    const float sc = TEMP_ON ? TEMPF : 1.0f;
    float cs[8];
#pragma unroll
    for (int j = 0; j < 8; j++) cs[j] = 0.0f;

#pragma unroll
    for (int i2 = 0; i2 < 4; i2++) {
#pragma unroll
        for (int h = 0; h < 2; h++) {
            float f[8];
            float mx = -1e30f;
#pragma unroll
            for (int j = 0; j < 8; j++) {
                f[j] = (h ? hi32(acc2[i2][j]) : lo32(acc2[i2][j])) * sc;
                mx = fmaxf(mx, f[j]);
            }
#pragma unroll
            for (int m = 4; m; m >>= 1)
                mx = fmaxf(mx, __shfl_xor_sync(0xffffffffu, mx, m));
            float s = 0.0f;
#pragma unroll
            for (int j = 0; j < 8; j++) { f[j] = __expf(f[j] - mx); s += f[j]; }
#pragma unroll
            for (int m = 4; m; m >>= 1)
                s += __shfl_xor_sync(0xffffffffu, s, m);
            float inv = 1.0f / s;
            const int n = n0 + nt * 8 + i2 * 2 + h;
            float* o = z + ((size_t)b * NN + n) * KK + kt * 8;
            float4 o0, o1;
            o0.x = f[0] * inv; o0.y = f[1] * inv; o0.z = f[2] * inv; o0.w = f[3] * inv;
            o1.x = f[4] * inv; o1.y = f[5] * inv; o1.z = f[6] * inv; o1.w = f[7] * inv;
            *(float4*)o = o0; *(float4*)(o + 4) = o1;
            if (TEMP_ON) {
#pragma unroll
                for (int j = 0; j < 8; j++) cs[j] += f[j] * inv;
            }
        }
    }

    if (TEMP_ON) {
        float* red = (float*)xs4;                  // 32 x 65 staging (8.3KB, safe reuse)
#pragma unroll
        for (int j = 0; j < 8; j++) red[nt * 65 + kt * 8 + j] = cs[j];
        __syncthreads();
        if (tid < 64) {
            float acc = 0.0f;
#pragma unroll 8
            for (int r = 0; r < 32; r++) acc += red[r * 65 + tid];
            g_Spart[(blockIdx.x * BB + b) * KK + tid] = acc;
        }
    }
}

// ---- GEMM2 partials: part[b,split,c,k] = sum_{n in split} x[b,c,n]*z[b,n,k]
// grid (NSPLIT, BB), 256 threads. Tile 256c x 64k, per-thread 8c x 8k (c-paired f32x2).
__global__ void __launch_bounds__(256)
k_gemm2(const float* __restrict__ x, const float* __restrict__ z) {
    __shared__ __align__(16) float xs[16 * 260];   // [n][c] transposed, stride 260 (16.6KB)
    __shared__ ull zsd[16 * 64];                   // dup b: [n][(k&7)*8+(k>>3)] (8KB)

    const int split = blockIdx.x, b = blockIdx.y;
    const int tid = threadIdx.x;
    const int kt = tid & 7;          // k = kt*8 .. +7
    const int ct = tid >> 3;         // c = ct*8 .. +7

    const float* __restrict__ xb = x + (size_t)b * CC * NN;
    const float* __restrict__ zb = z + (size_t)b * NN * KK;
    const int ns0 = split * (NN / NSPLIT);         // 512-wide n chunk

    ull acc2[4][8];                  // [c-pair][k]
#pragma unroll
    for (int i = 0; i < 4; i++)
#pragma unroll
        for (int j = 0; j < 8; j++) acc2[i][j] = 0ull;

    for (int t = 0; t < (NN / NSPLIT) / 16; t++) {
        const int nn = ns0 + t * 16;
#pragma unroll
        for (int it = 0; it < 4; it++) {           // x: 256c x 16n, store transposed
            int idx = it * 256 + tid, r = idx >> 2, q = idx & 3;
            float4 v = *(const float4*)(xb + (size_t)r * NN + nn + q * 4);
            xs[(q * 4 + 0) * 260 + r] = v.x;
            xs[(q * 4 + 1) * 260 + r] = v.y;
            xs[(q * 4 + 2) * 260 + r] = v.z;
            xs[(q * 4 + 3) * 260 + r] = v.w;
        }
        {                                          // z: 16n x 64k, duplicated
            int r = tid >> 4, q = (tid & 15) * 4;
            float4 v = *(const float4*)(zb + (size_t)(nn + r) * KK + q);
            float f[4] = {v.x, v.y, v.z, v.w};
#pragma unroll
            for (int e = 0; e < 4; e++) zsd[r * 64 + koff(q + e)] = dup2(f[e]);
        }
        __syncthreads();

#pragma unroll
        for (int n = 0; n < 16; n++) {
            const ulonglong2* xr = (const ulonglong2*)(&xs[n * 260 + ct * 8]);
            ulonglong2 A0 = xr[0], A1 = xr[1];
            ull a2[4] = {A0.x, A0.y, A1.x, A1.y};
            const ull* br = &zsd[n * 64 + kt];
#pragma unroll
            for (int j = 0; j < 8; j++) {
                ull bd = br[j * 8];
#pragma unroll
                for (int i = 0; i < 4; i++) acc2[i][j] = fma2(a2[i], bd, acc2[i][j]);
            }
        }
        __syncthreads();
    }

    // write partials (unique slot per block -> deterministic)
#pragma unroll
    for (int c2 = 0; c2 < 4; c2++) {
#pragma unroll
        for (int h = 0; h < 2; h++) {
            const int c = ct * 8 + c2 * 2 + h;
            float* o = g_part + (((size_t)(b * NSPLIT + split)) * CC + c) * KK + kt * 8;
            float4 o0, o1;
            o0.x = h ? hi32(acc2[c2][0]) : lo32(acc2[c2][0]);
            o0.y = h ? hi32(acc2[c2][1]) : lo32(acc2[c2][1]);
            o0.z = h ? hi32(acc2[c2][2]) : lo32(acc2[c2][2]);
            o0.w = h ? hi32(acc2[c2][3]) : lo32(acc2[c2][3]);
            o1.x = h ? hi32(acc2[c2][4]) : lo32(acc2[c2][4]);
            o1.y = h ? hi32(acc2[c2][5]) : lo32(acc2[c2][5]);
            o1.z = h ? hi32(acc2[c2][6]) : lo32(acc2[c2][6]);
            o1.w = h ? hi32(acc2[c2][7]) : lo32(acc2[c2][7]);
            *(float4*)o = o0; *(float4*)(o + 4) = o1;
        }
    }
}

// -------- S[b,k] = sum over n-blocks of Spart --------
__global__ void k_sumS() {
    int b = blockIdx.x, k = threadIdx.x;
    float s = 0.0f;
    for (int r = 0; r < NBLK1; r++) s += g_Spart[(r * BB + b) * KK + k];
    g_S[b * KK + k] = s;
}

// -------- m'[b,c,k] = (sum_splits part) / (EPS + S[b,k]) --------
__global__ void k_reduceScale() {
    int c = blockIdx.x, b = blockIdx.y, k = threadIdx.x;
    float s = 0.0f;
    size_t base = (((size_t)(b * NSPLIT)) * CC + c) * KK + k;
#pragma unroll 4
    for (int sp = 0; sp < NSPLIT; sp++) s += g_part[base + (size_t)sp * CC * KK];
    g_mtmp[(b * CC + c) * KK + k] = s / (EPSF + g_S[b * KK + k]);
}

// -------- l2-normalize m over C --------
__global__ void k_l2norm() {
    int k = blockIdx.x, b = blockIdx.y, c = threadIdx.x;   // 256 threads
    float v = g_mtmp[(b * CC + c) * KK + k];
    float sq = v * v;
#pragma unroll
    for (int m = 16; m; m >>= 1) sq += __shfl_xor_sync(0xffffffffu, sq, m);
    __shared__ float red[8];
    if ((threadIdx.x & 31) == 0) red[threadIdx.x >> 5] = sq;
    __syncthreads();
    float total = 0.0f;
#pragma unroll
    for (int w = 0; w < 8; w++) total += red[w];
    g_m[(b * CC + c) * KK + k] = v / (EPSF + sqrtf(total));
}

// -------- launch --------
extern "C" void kernel_launch(void* const* d_in, const int* in_sizes, int n_in,
                              void* d_out, int out_size) {
    const float* x  = (const float*)d_in[0];
    const float* mu = (const float*)d_in[1];
    if (n_in >= 2 && in_sizes[0] < in_sizes[1]) { const float* t = x; x = mu; mu = t; }
    float* z = (float*)d_out;                      // [B,N,K] doubles as z scratch

    k_init<<<(BB * CC * KK) / 256, 256>>>(mu);

    for (int s = 0; s < EM_STEPS; s++) {
        k_gemm1<true><<<dim3(NBLK1, BB), 256>>>(x, z);
        k_gemm2<<<dim3(NSPLIT, BB), 256>>>(x, z);
        k_sumS<<<BB, KK>>>();
        k_reduceScale<<<dim3(CC, BB), KK>>>();
        k_l2norm<<<dim3(KK, BB), 256>>>();
    }
    // final soft assignment: NO temperature in the reference here
    k_gemm1<false><<<dim3(NBLK1, BB), 256>>>(x, z);
}

// round 9
// speedup vs baseline: 1.3155x; 1.3155x over previous
#include <cuda_runtime.h>
#include <cuda_bf16.h>
#include <cstdint>
#include <math.h>

#define BB   16
#define CC   256
#define NN   16384
#define KK   64
#define TEMPF 20.0f
#define EPSF  1e-6f
#define EM_STEPS 3
#define NSPLIT 32
#define NBLK1 (NN/128)      // 128 GEMM1 n-blocks

// -------- scratch (no allocations allowed -> device globals) --------
__device__ __align__(16) __nv_bfloat16 g_xthi[(size_t)BB*NN*CC];  // x^T hi [b][n][c]
__device__ __align__(16) __nv_bfloat16 g_xtlo[(size_t)BB*NN*CC];
__device__ __align__(16) __nv_bfloat16 g_xchi[(size_t)BB*CC*NN];  // x hi   [b][c][n]
__device__ __align__(16) __nv_bfloat16 g_xclo[(size_t)BB*CC*NN];
__device__ __align__(16) __nv_bfloat16 g_zthi[(size_t)BB*KK*NN];  // z^T hi [b][k][n]
__device__ __align__(16) __nv_bfloat16 g_ztlo[(size_t)BB*KK*NN];
__device__ __align__(16) __nv_bfloat16 g_mthi[BB*KK*CC];          // m^T hi [b][k][c]
__device__ __align__(16) __nv_bfloat16 g_mtlo[BB*KK*CC];
__device__ float g_mtmp [BB*CC*KK];
__device__ float g_S    [BB*KK];
__device__ float g_Spart[NBLK1*BB*KK];
__device__ float g_part [(size_t)BB*NSPLIT*CC*KK];

// -------- helpers --------
__device__ __forceinline__ uint32_t smem_u32(const void* p) {
    uint32_t a;
    asm("{ .reg .u64 t; cvta.to.shared.u64 t, %1; cvt.u32.u64 %0, t; }" : "=r"(a) : "l"(p));
    return a;
}
__device__ __forceinline__ void ldm_x4(uint32_t r[4], uint32_t addr) {
    asm volatile("ldmatrix.sync.aligned.m8n8.x4.shared.b16 {%0,%1,%2,%3}, [%4];"
        : "=r"(r[0]), "=r"(r[1]), "=r"(r[2]), "=r"(r[3]) : "r"(addr));
}
__device__ __forceinline__ void mma16816(float c[4], const uint32_t a[4], uint32_t b0, uint32_t b1) {
    asm volatile("mma.sync.aligned.m16n8k16.row.col.f32.bf16.bf16.f32 "
        "{%0,%1,%2,%3}, {%4,%5,%6,%7}, {%8,%9}, {%0,%1,%2,%3};"
        : "+f"(c[0]), "+f"(c[1]), "+f"(c[2]), "+f"(c[3])
        : "r"(a[0]), "r"(a[1]), "r"(a[2]), "r"(a[3]), "r"(b0), "r"(b1));
}
__device__ __forceinline__ void split_bf16(float v, __nv_bfloat16& hi, __nv_bfloat16& lo) {
    hi = __float2bfloat16_rn(v);
    lo = __float2bfloat16_rn(v - __bfloat162float(hi));
}

// smem union: GEMM tiles vs epilogue staging
union Smem {
    struct {                                     // mainloop tiles
        __nv_bfloat16 ah[128][40], al[128][40];  // A rows x 32ctr (+8 pad)
        __nv_bfloat16 bh[64][40],  bl[64][40];   // B^T: 64 k-rows x 32ctr (+8 pad)
    } g;                                         // 30720 B
    struct {                                     // EPI0: z^T bf16 staging
        __nv_bfloat16 zh[64][144], zl[64][144];  // rows 288B (16B mult)
    } e0;                                        // 36864 B
    struct {                                     // EPI1/2: f32 staging
        float zs[128][72];                       // rows 288B
    } e1;                                        // 36864 B
};

// -------- prepass: x [b][c][n] fp32 -> split bf16 in both orientations --------
__global__ void k_prep(const float* __restrict__ x) {
    __shared__ float tbuf[32][33];
    const int b = blockIdx.z, n0 = blockIdx.x * 32, c0 = blockIdx.y * 32;
    const int tx = threadIdx.x, ty = threadIdx.y;
#pragma unroll
    for (int j = 0; j < 4; j++) {
        int c = c0 + ty + 8 * j;
        size_t o = ((size_t)b * CC + c) * NN + n0 + tx;
        float v = x[o];
        tbuf[ty + 8 * j][tx] = v;
        __nv_bfloat16 hi, lo; split_bf16(v, hi, lo);
        g_xchi[o] = hi; g_xclo[o] = lo;
    }
    __syncthreads();
#pragma unroll
    for (int j = 0; j < 4; j++) {
        float v = tbuf[tx][ty + 8 * j];
        __nv_bfloat16 hi, lo; split_bf16(v, hi, lo);
        size_t o = ((size_t)b * NN + n0 + ty + 8 * j) * CC + c0 + tx;
        g_xthi[o] = hi; g_xtlo[o] = lo;
    }
}

// -------- init m^T from mu (broadcast over batches) --------
__global__ void k_initm(const float* __restrict__ mu) {
    int idx = blockIdx.x * 256 + threadIdx.x;       // over B*K*C, c fastest
    int c = idx & (CC - 1);
    int k = (idx >> 8) & (KK - 1);
    __nv_bfloat16 hi, lo; split_bf16(mu[c * KK + k], hi, lo);
    g_mthi[idx] = hi; g_mtlo[idx] = lo;
}

// ---- unified MMA kernel ----
// EPI 0: GEMM1 EM step  : softmax(TEMP*logits) -> z^T split bf16 + column-sum partials
// EPI 1: GEMM1 final    : softmax(logits) -> fp32 z to d_out
// EPI 2: GEMM2 partials : raw fp32 partial sums to g_part
template<int EPI>
__global__ void __launch_bounds__(256)
k_mma(float* __restrict__ zout) {
    __shared__ Smem sm;
    const int tid  = threadIdx.x;
    const int lane = tid & 31, warp = tid >> 5;
    const int g = lane >> 2, t = lane & 3;
    const int warp_row = warp * 16;

    const __nv_bfloat16 *Ah, *Al, *Bh, *Bl;
    size_t sA, sB; int ctr0, iters, b, rowbase;
    if (EPI < 2) {
        b = blockIdx.y; rowbase = blockIdx.x * 128;
        Ah = g_xthi + ((size_t)b * NN + rowbase) * CC;
        Al = g_xtlo + ((size_t)b * NN + rowbase) * CC;
        Bh = g_mthi + (size_t)b * KK * CC;
        Bl = g_mtlo + (size_t)b * KK * CC;
        sA = CC; sB = CC; ctr0 = 0; iters = CC / 32;
    } else {
        b = blockIdx.z; rowbase = blockIdx.x * 128;
        Ah = g_xchi + ((size_t)b * CC + rowbase) * NN;
        Al = g_xclo + ((size_t)b * CC + rowbase) * NN;
        Bh = g_zthi + (size_t)b * KK * NN;
        Bl = g_ztlo + (size_t)b * KK * NN;
        sA = NN; sB = NN;
        ctr0 = blockIdx.y * (NN / NSPLIT); iters = (NN / NSPLIT) / 32;
    }

    float acc[8][4];
#pragma unroll
    for (int j = 0; j < 8; j++)
#pragma unroll
        for (int r = 0; r < 4; r++) acc[j][r] = 0.0f;

    const int lrow = tid >> 1, lseg = tid & 1;
    for (int it = 0; it < iters; it++) {
        const int c0 = ctr0 + it * 32;
        {   // A tile: 128 rows x 32 ctr
            const __nv_bfloat16* s = Ah + (size_t)lrow * sA + c0 + lseg * 16;
            *(uint4*)&sm.g.ah[lrow][lseg * 16]     = *(const uint4*)s;
            *(uint4*)&sm.g.ah[lrow][lseg * 16 + 8] = *(const uint4*)(s + 8);
            s = Al + (size_t)lrow * sA + c0 + lseg * 16;
            *(uint4*)&sm.g.al[lrow][lseg * 16]     = *(const uint4*)s;
            *(uint4*)&sm.g.al[lrow][lseg * 16 + 8] = *(const uint4*)(s + 8);
        }
        if (tid < 128) {  // B tile: 64 k-rows x 32 ctr
            const __nv_bfloat16* s = Bh + (size_t)lrow * sB + c0 + lseg * 16;
            *(uint4*)&sm.g.bh[lrow][lseg * 16]     = *(const uint4*)s;
            *(uint4*)&sm.g.bh[lrow][lseg * 16 + 8] = *(const uint4*)(s + 8);
            s = Bl + (size_t)lrow * sB + c0 + lseg * 16;
            *(uint4*)&sm.g.bl[lrow][lseg * 16]     = *(const uint4*)s;
            *(uint4*)&sm.g.bl[lrow][lseg * 16 + 8] = *(const uint4*)(s + 8);
        }
        __syncthreads();

#pragma unroll
        for (int ks = 0; ks < 2; ks++) {
            const int lr = lane & 7, lq = lane >> 3;
            uint32_t ah4[4], al4[4];
            ldm_x4(ah4, smem_u32(&sm.g.ah[warp_row + lr + (lq & 1) * 8][ks * 16 + (lq >> 1) * 8]));
            ldm_x4(al4, smem_u32(&sm.g.al[warp_row + lr + (lq & 1) * 8][ks * 16 + (lq >> 1) * 8]));
#pragma unroll
            for (int j = 0; j < 8; j++) {
                uint32_t bh0 = *(const uint32_t*)&sm.g.bh[j * 8 + g][ks * 16 + 2 * t];
                uint32_t bh1 = *(const uint32_t*)&sm.g.bh[j * 8 + g][ks * 16 + 2 * t + 8];
                uint32_t bl0 = *(const uint32_t*)&sm.g.bl[j * 8 + g][ks * 16 + 2 * t];
                uint32_t bl1 = *(const uint32_t*)&sm.g.bl[j * 8 + g][ks * 16 + 2 * t + 8];
                mma16816(acc[j], ah4, bh0, bh1);   // hi*hi
                mma16816(acc[j], ah4, bl0, bl1);   // hi*lo
                mma16816(acc[j], al4, bh0, bh1);   // lo*hi
            }
        }
        __syncthreads();
    }

    if (EPI == 2) {
        // stage fp32 and write partials coalesced
#pragma unroll
        for (int j = 0; j < 8; j++) {
            sm.e1.zs[warp_row + g    ][8 * j + 2 * t    ] = acc[j][0];
            sm.e1.zs[warp_row + g    ][8 * j + 2 * t + 1] = acc[j][1];
            sm.e1.zs[warp_row + g + 8][8 * j + 2 * t    ] = acc[j][2];
            sm.e1.zs[warp_row + g + 8][8 * j + 2 * t + 1] = acc[j][3];
        }
        __syncthreads();
        const int split = blockIdx.y;
        float* dst = g_part + (((size_t)(b * NSPLIT + split)) * CC + rowbase + lrow) * KK + lseg * 32;
        const float* src = &sm.e1.zs[lrow][lseg * 32];
#pragma unroll
        for (int q = 0; q < 8; q++) ((float4*)dst)[q] = ((const float4*)src)[q];
        return;
    }

    // GEMM1 epilogues: softmax over k (rows warp_row+g and warp_row+g+8)
    const float sc = (EPI == 0) ? TEMPF : 1.0f;
    float mxA = -1e30f, mxB = -1e30f;
#pragma unroll
    for (int j = 0; j < 8; j++) {
        acc[j][0] *= sc; acc[j][1] *= sc; acc[j][2] *= sc; acc[j][3] *= sc;
        mxA = fmaxf(mxA, fmaxf(acc[j][0], acc[j][1]));
        mxB = fmaxf(mxB, fmaxf(acc[j][2], acc[j][3]));
    }
    mxA = fmaxf(mxA, __shfl_xor_sync(0xffffffffu, mxA, 1));
    mxA = fmaxf(mxA, __shfl_xor_sync(0xffffffffu, mxA, 2));
    mxB = fmaxf(mxB, __shfl_xor_sync(0xffffffffu, mxB, 1));
    mxB = fmaxf(mxB, __shfl_xor_sync(0xffffffffu, mxB, 2));
    float sumA = 0.0f, sumB = 0.0f;
#pragma unroll
    for (int j = 0; j < 8; j++) {
        acc[j][0] = __expf(acc[j][0] - mxA); acc[j][1] = __expf(acc[j][1] - mxA);
        acc[j][2] = __expf(acc[j][2] - mxB); acc[j][3] = __expf(acc[j][3] - mxB);
        sumA += acc[j][0] + acc[j][1];
        sumB += acc[j][2] + acc[j][3];
    }
    sumA += __shfl_xor_sync(0xffffffffu, sumA, 1);
    sumA += __shfl_xor_sync(0xffffffffu, sumA, 2);
    sumB += __shfl_xor_sync(0xffffffffu, sumB, 1);
    sumB += __shfl_xor_sync(0xffffffffu, sumB, 2);
    const float invA = 1.0f / sumA, invB = 1.0f / sumB;

    if (EPI == 1) {
#pragma unroll
        for (int j = 0; j < 8; j++) {
            sm.e1.zs[warp_row + g    ][8 * j + 2 * t    ] = acc[j][0] * invA;
            sm.e1.zs[warp_row + g    ][8 * j + 2 * t + 1] = acc[j][1] * invA;
            sm.e1.zs[warp_row + g + 8][8 * j + 2 * t    ] = acc[j][2] * invB;
            sm.e1.zs[warp_row + g + 8][8 * j + 2 * t + 1] = acc[j][3] * invB;
        }
        __syncthreads();
        float* dst = zout + ((size_t)b * NN + rowbase + lrow) * KK + lseg * 32;
        const float* src = &sm.e1.zs[lrow][lseg * 32];
#pragma unroll
        for (int q = 0; q < 8; q++) ((float4*)dst)[q] = ((const float4*)src)[q];
        return;
    }

    // EPI == 0: stage z^T split bf16
#pragma unroll
    for (int j = 0; j < 8; j++) {
        __nv_bfloat16 hi, lo;
        split_bf16(acc[j][0] * invA, hi, lo);
        sm.e0.zh[8 * j + 2 * t    ][warp_row + g    ] = hi; sm.e0.zl[8 * j + 2 * t    ][warp_row + g    ] = lo;
        split_bf16(acc[j][1] * invA, hi, lo);
        sm.e0.zh[8 * j + 2 * t + 1][warp_row + g    ] = hi; sm.e0.zl[8 * j + 2 * t + 1][warp_row + g    ] = lo;
        split_bf16(acc[j][2] * invB, hi, lo);
        sm.e0.zh[8 * j + 2 * t    ][warp_row + g + 8] = hi; sm.e0.zl[8 * j + 2 * t    ][warp_row + g + 8] = lo;
        split_bf16(acc[j][3] * invB, hi, lo);
        sm.e0.zh[8 * j + 2 * t + 1][warp_row + g + 8] = hi; sm.e0.zl[8 * j + 2 * t + 1][warp_row + g + 8] = lo;
    }
    __syncthreads();
    {   // coalesced z^T global write: 64 k-rows x 128 n
        const int k = tid >> 2, q = tid & 3;
        __nv_bfloat16* dh = g_zthi + ((size_t)(b * KK + k)) * NN + rowbase + q * 32;
        __nv_bfloat16* dl = g_ztlo + ((size_t)(b * KK + k)) * NN + rowbase + q * 32;
        const __nv_bfloat16* sh = &sm.e0.zh[k][q * 32];
        const __nv_bfloat16* sl = &sm.e0.zl[k][q * 32];
#pragma unroll
        for (int r = 0; r < 4; r++) {
            ((uint4*)dh)[r] = ((const uint4*)sh)[r];
            ((uint4*)dl)[r] = ((const uint4*)sl)[r];
        }
    }
    if (tid < 64) {  // deterministic column sums over this n-block
        float s = 0.0f;
#pragma unroll 8
        for (int n = 0; n < 128; n++)
            s += __bfloat162float(sm.e0.zh[tid][n]) + __bfloat162float(sm.e0.zl[tid][n]);
        g_Spart[(blockIdx.x * BB + b) * KK + tid] = s;
    }
}

// -------- small reductions --------
__global__ void k_sumS() {
    int b = blockIdx.x, k = threadIdx.x;
    float s = 0.0f;
    for (int r = 0; r < NBLK1; r++) s += g_Spart[(r * BB + b) * KK + k];
    g_S[b * KK + k] = s;
}
__global__ void k_reduceScale() {
    int c = blockIdx.x, b = blockIdx.y, k = threadIdx.x;
    float s = 0.0f;
    size_t base = (((size_t)(b * NSPLIT)) * CC + c) * KK + k;
#pragma unroll 4
    for (int sp = 0; sp < NSPLIT; sp++) s += g_part[base + (size_t)sp * CC * KK];
    g_mtmp[(b * CC + c) * KK + k] = s / (EPSF + g_S[b * KK + k]);
}
__global__ void k_l2norm() {
    int k = blockIdx.x, b = blockIdx.y, c = threadIdx.x;   // 256 threads
    float v = g_mtmp[(b * CC + c) * KK + k];
    float sq = v * v;
#pragma unroll
    for (int m = 16; m; m >>= 1) sq += __shfl_xor_sync(0xffffffffu, sq, m);
    __shared__ float red[8];
    if ((threadIdx.x & 31) == 0) red[threadIdx.x >> 5] = sq;
    __syncthreads();
    float total = 0.0f;
#pragma unroll
    for (int w = 0; w < 8; w++) total += red[w];
    float out = v / (EPSF + sqrtf(total));
    __nv_bfloat16 hi, lo; split_bf16(out, hi, lo);
    size_t o = ((size_t)b * KK + k) * CC + c;
    g_mthi[o] = hi; g_mtlo[o] = lo;
}

// -------- launch --------
extern "C" void kernel_launch(void* const* d_in, const int* in_sizes, int n_in,
                              void* d_out, int out_size) {
    const float* x  = (const float*)d_in[0];
    const float* mu = (const float*)d_in[1];
    if (n_in >= 2 && in_sizes[0] < in_sizes[1]) { const float* tp = x; x = mu; mu = tp; }
    float* z = (float*)d_out;

    k_prep<<<dim3(NN / 32, CC / 32, BB), dim3(32, 8)>>>(x);
    k_initm<<<(BB * KK * CC) / 256, 256>>>(mu);

    for (int s = 0; s < EM_STEPS; s++) {
        k_mma<0><<<dim3(NBLK1, BB), 256>>>(nullptr);
        k_mma<2><<<dim3(CC / 128, NSPLIT, BB), 256>>>(nullptr);
        k_sumS<<<BB, KK>>>();
        k_reduceScale<<<dim3(CC, BB), KK>>>();
        k_l2norm<<<dim3(KK, BB), 256>>>();
    }
    // final soft assignment: NO temperature in the reference here
    k_mma<1><<<dim3(NBLK1, BB), 256>>>(z);
}

// round 10
// speedup vs baseline: 1.6257x; 1.2358x over previous
#include <cuda_runtime.h>
#include <cuda_bf16.h>
#include <cstdint>
#include <math.h>

#define BB   16
#define CC   256
#define NN   16384
#define KK   64
#define TEMPF 20.0f
#define EPSF  1e-6f
#define EM_STEPS 3
#define NSPLIT 32
#define NBLK1 (NN/128)      // 128 GEMM1 n-blocks

// -------- scratch (no allocations allowed -> device globals) --------
__device__ __align__(16) __nv_bfloat16 g_xthi[(size_t)BB*NN*CC];  // x^T hi [b][n][c]
__device__ __align__(16) __nv_bfloat16 g_xtlo[(size_t)BB*NN*CC];
__device__ __align__(16) __nv_bfloat16 g_xchi[(size_t)BB*CC*NN];  // x hi   [b][c][n]
__device__ __align__(16) __nv_bfloat16 g_xclo[(size_t)BB*CC*NN];
__device__ __align__(16) __nv_bfloat16 g_zthi[(size_t)BB*KK*NN];  // z^T hi [b][k][n]
__device__ __align__(16) __nv_bfloat16 g_ztlo[(size_t)BB*KK*NN];
__device__ __align__(16) __nv_bfloat16 g_mthi[BB*KK*CC];          // m^T hi [b][k][c]
__device__ __align__(16) __nv_bfloat16 g_mtlo[BB*KK*CC];
__device__ float g_mtmp [BB*CC*KK];
__device__ float g_S    [BB*KK];
__device__ float g_Spart[NBLK1*BB*KK];
__device__ float g_part [(size_t)BB*NSPLIT*CC*KK];

// -------- helpers --------
__device__ __forceinline__ uint32_t smem_u32(const void* p) {
    uint32_t a;
    asm("{ .reg .u64 t; cvta.to.shared.u64 t, %1; cvt.u32.u64 %0, t; }" : "=r"(a) : "l"(p));
    return a;
}
__device__ __forceinline__ void ldm_x4(uint32_t r[4], uint32_t addr) {
    asm volatile("ldmatrix.sync.aligned.m8n8.x4.shared.b16 {%0,%1,%2,%3}, [%4];"
        : "=r"(r[0]), "=r"(r[1]), "=r"(r[2]), "=r"(r[3]) : "r"(addr));
}
__device__ __forceinline__ void mma16816(float c[4], const uint32_t a[4], uint32_t b0, uint32_t b1) {
    asm volatile("mma.sync.aligned.m16n8k16.row.col.f32.bf16.bf16.f32 "
        "{%0,%1,%2,%3}, {%4,%5,%6,%7}, {%8,%9}, {%0,%1,%2,%3};"
        : "+f"(c[0]), "+f"(c[1]), "+f"(c[2]), "+f"(c[3])
        : "r"(a[0]), "r"(a[1]), "r"(a[2]), "r"(a[3]), "r"(b0), "r"(b1));
}
__device__ __forceinline__ void split_bf16(float v, __nv_bfloat16& hi, __nv_bfloat16& lo) {
    hi = __float2bfloat16_rn(v);
    lo = __float2bfloat16_rn(v - __bfloat162float(hi));
}
#define CP16(d, s)  asm volatile("cp.async.cg.shared.global [%0], [%1], 16;" :: "r"(d), "l"(s))
#define CP_COMMIT() asm volatile("cp.async.commit_group;" ::: "memory")
#define CP_WAIT1()  asm volatile("cp.async.wait_group 1;" ::: "memory")
#define CP_WAIT0()  asm volatile("cp.async.wait_group 0;" ::: "memory")

// smem layouts over one dynamic buffer
struct Tiles {                                   // one pipeline stage: 30720 B
    __nv_bfloat16 ah[128][40], al[128][40];      // A rows x 32ctr (+8 pad)
    __nv_bfloat16 bh[64][40],  bl[64][40];       // B^T: 64 k-rows x 32ctr (+8 pad)
};
struct E0 { __nv_bfloat16 zh[64][144], zl[64][144]; };  // 36864 B
struct E1 { float zs[128][72]; };                        // 36864 B
#define SMEM_MAIN 61440                           // 2 * sizeof(Tiles)

// -------- prepass: x [b][c][n] fp32 -> split bf16 in both orientations --------
__global__ void k_prep(const float* __restrict__ x) {
    __shared__ float tbuf[32][33];
    const int b = blockIdx.z, n0 = blockIdx.x * 32, c0 = blockIdx.y * 32;
    const int tx = threadIdx.x, ty = threadIdx.y;
#pragma unroll
    for (int j = 0; j < 4; j++) {
        int c = c0 + ty + 8 * j;
        size_t o = ((size_t)b * CC + c) * NN + n0 + tx;
        float v = x[o];
        tbuf[ty + 8 * j][tx] = v;
        __nv_bfloat16 hi, lo; split_bf16(v, hi, lo);
        g_xchi[o] = hi; g_xclo[o] = lo;
    }
    __syncthreads();
#pragma unroll
    for (int j = 0; j < 4; j++) {
        float v = tbuf[tx][ty + 8 * j];
        __nv_bfloat16 hi, lo; split_bf16(v, hi, lo);
        size_t o = ((size_t)b * NN + n0 + ty + 8 * j) * CC + c0 + tx;
        g_xthi[o] = hi; g_xtlo[o] = lo;
    }
}

// -------- init m^T from mu (broadcast over batches) --------
__global__ void k_initm(const float* __restrict__ mu) {
    int idx = blockIdx.x * 256 + threadIdx.x;       // over B*K*C, c fastest
    int c = idx & (CC - 1);
    int k = (idx >> 8) & (KK - 1);
    __nv_bfloat16 hi, lo; split_bf16(mu[c * KK + k], hi, lo);
    g_mthi[idx] = hi; g_mtlo[idx] = lo;
}

// ---- unified MMA kernel (2-stage cp.async pipeline, ldmatrix A+B) ----
// EPI 0: GEMM1 EM step  : softmax(TEMP*logits) -> z^T split bf16 + column-sum partials
// EPI 1: GEMM1 final    : softmax(logits) -> fp32 z to d_out
// EPI 2: GEMM2 partials : raw fp32 partial sums to g_part
template<int EPI>
__global__ void __launch_bounds__(256)
k_mma(float* __restrict__ zout) {
    extern __shared__ __align__(16) char dynsmem[];
    Tiles* tiles = (Tiles*)dynsmem;
    E0* e0 = (E0*)dynsmem;
    E1* e1 = (E1*)dynsmem;

    const int tid  = threadIdx.x;
    const int lane = tid & 31, warp = tid >> 5;
    const int g = lane >> 2, t = lane & 3;
    const int warp_row = warp * 16;

    const __nv_bfloat16 *Ah, *Al, *Bh, *Bl;
    size_t sA, sB; int ctr0, iters, b, rowbase;
    if (EPI < 2) {
        b = blockIdx.y; rowbase = blockIdx.x * 128;
        Ah = g_xthi + ((size_t)b * NN + rowbase) * CC;
        Al = g_xtlo + ((size_t)b * NN + rowbase) * CC;
        Bh = g_mthi + (size_t)b * KK * CC;
        Bl = g_mtlo + (size_t)b * KK * CC;
        sA = CC; sB = CC; ctr0 = 0; iters = CC / 32;
    } else {
        b = blockIdx.z; rowbase = blockIdx.x * 128;
        Ah = g_xchi + ((size_t)b * CC + rowbase) * NN;
        Al = g_xclo + ((size_t)b * CC + rowbase) * NN;
        Bh = g_zthi + (size_t)b * KK * NN;
        Bl = g_ztlo + (size_t)b * KK * NN;
        sA = NN; sB = NN;
        ctr0 = blockIdx.y * (NN / NSPLIT); iters = (NN / NSPLIT) / 32;
    }

    float acc[8][4];
#pragma unroll
    for (int j = 0; j < 8; j++)
#pragma unroll
        for (int r = 0; r < 4; r++) acc[j][r] = 0.0f;

    const int lrow = tid >> 1, lseg = tid & 1;

    // async fill of one stage (A: 256 threads, B: first 128 threads)
    auto fill = [&](int it, int buf) {
        const int c0 = ctr0 + it * 32;
        Tiles& T = tiles[buf];
        {
            uint32_t d = smem_u32(&T.ah[lrow][lseg * 16]);
            const __nv_bfloat16* s = Ah + (size_t)lrow * sA + c0 + lseg * 16;
            CP16(d, s); CP16(d + 16, s + 8);
            d = smem_u32(&T.al[lrow][lseg * 16]);
            s = Al + (size_t)lrow * sA + c0 + lseg * 16;
            CP16(d, s); CP16(d + 16, s + 8);
        }
        if (tid < 128) {
            uint32_t d = smem_u32(&T.bh[lrow][lseg * 16]);
            const __nv_bfloat16* s = Bh + (size_t)lrow * sB + c0 + lseg * 16;
            CP16(d, s); CP16(d + 16, s + 8);
            d = smem_u32(&T.bl[lrow][lseg * 16]);
            s = Bl + (size_t)lrow * sB + c0 + lseg * 16;
            CP16(d, s); CP16(d + 16, s + 8);
        }
        CP_COMMIT();
    };

    fill(0, 0);
    for (int it = 0; it < iters; it++) {
        if (it + 1 < iters) { fill(it + 1, (it + 1) & 1); CP_WAIT1(); }
        else                { CP_WAIT0(); }
        __syncthreads();
        Tiles& T = tiles[it & 1];

#pragma unroll
        for (int ks = 0; ks < 2; ks++) {
            const int lr = lane & 7, lq = lane >> 3;
            uint32_t ah4[4], al4[4];
            ldm_x4(ah4, smem_u32(&T.ah[warp_row + lr + (lq & 1) * 8][ks * 16 + (lq >> 1) * 8]));
            ldm_x4(al4, smem_u32(&T.al[warp_row + lr + (lq & 1) * 8][ks * 16 + (lq >> 1) * 8]));
            // B fragments via ldmatrix.x4: quad q -> row jp*16+(q>>1)*8+lr, col ks*16+(q&1)*8
            uint32_t bhf[16], blf[16];
#pragma unroll
            for (int jp = 0; jp < 4; jp++) {
                uint32_t addr_h = smem_u32(&T.bh[jp * 16 + (lq >> 1) * 8 + lr][ks * 16 + (lq & 1) * 8]);
                uint32_t addr_l = smem_u32(&T.bl[jp * 16 + (lq >> 1) * 8 + lr][ks * 16 + (lq & 1) * 8]);
                ldm_x4(&bhf[jp * 4], addr_h);
                ldm_x4(&blf[jp * 4], addr_l);
            }
#pragma unroll
            for (int j = 0; j < 8; j++) {
                const int jp = j >> 1, sub = j & 1;
                uint32_t bh0 = bhf[jp * 4 + sub * 2], bh1 = bhf[jp * 4 + sub * 2 + 1];
                uint32_t bl0 = blf[jp * 4 + sub * 2], bl1 = blf[jp * 4 + sub * 2 + 1];
                mma16816(acc[j], ah4, bh0, bh1);   // hi*hi
                mma16816(acc[j], ah4, bl0, bl1);   // hi*lo
                mma16816(acc[j], al4, bh0, bh1);   // lo*hi
            }
        }
        __syncthreads();
    }

    if (EPI == 2) {
#pragma unroll
        for (int j = 0; j < 8; j++) {
            e1->zs[warp_row + g    ][8 * j + 2 * t    ] = acc[j][0];
            e1->zs[warp_row + g    ][8 * j + 2 * t + 1] = acc[j][1];
            e1->zs[warp_row + g + 8][8 * j + 2 * t    ] = acc[j][2];
            e1->zs[warp_row + g + 8][8 * j + 2 * t + 1] = acc[j][3];
        }
        __syncthreads();
        const int split = blockIdx.y;
        float* dst = g_part + (((size_t)(b * NSPLIT + split)) * CC + rowbase + lrow) * KK + lseg * 32;
        const float* src = &e1->zs[lrow][lseg * 32];
#pragma unroll
        for (int q = 0; q < 8; q++) ((float4*)dst)[q] = ((const float4*)src)[q];
        return;
    }

    // GEMM1 epilogues: softmax over k (rows warp_row+g and warp_row+g+8)
    const float sc = (EPI == 0) ? TEMPF : 1.0f;
    float mxA = -1e30f, mxB = -1e30f;
#pragma unroll
    for (int j = 0; j < 8; j++) {
        acc[j][0] *= sc; acc[j][1] *= sc; acc[j][2] *= sc; acc[j][3] *= sc;
        mxA = fmaxf(mxA, fmaxf(acc[j][0], acc[j][1]));
        mxB = fmaxf(mxB, fmaxf(acc[j][2], acc[j][3]));
    }
    mxA = fmaxf(mxA, __shfl_xor_sync(0xffffffffu, mxA, 1));
    mxA = fmaxf(mxA, __shfl_xor_sync(0xffffffffu, mxA, 2));
    mxB = fmaxf(mxB, __shfl_xor_sync(0xffffffffu, mxB, 1));
    mxB = fmaxf(mxB, __shfl_xor_sync(0xffffffffu, mxB, 2));
    float sumA = 0.0f, sumB = 0.0f;
#pragma unroll
    for (int j = 0; j < 8; j++) {
        acc[j][0] = __expf(acc[j][0] - mxA); acc[j][1] = __expf(acc[j][1] - mxA);
        acc[j][2] = __expf(acc[j][2] - mxB); acc[j][3] = __expf(acc[j][3] - mxB);
        sumA += acc[j][0] + acc[j][1];
        sumB += acc[j][2] + acc[j][3];
    }
    sumA += __shfl_xor_sync(0xffffffffu, sumA, 1);
    sumA += __shfl_xor_sync(0xffffffffu, sumA, 2);
    sumB += __shfl_xor_sync(0xffffffffu, sumB, 1);
    sumB += __shfl_xor_sync(0xffffffffu, sumB, 2);
    const float invA = 1.0f / sumA, invB = 1.0f / sumB;

    if (EPI == 1) {
#pragma unroll
        for (int j = 0; j < 8; j++) {
            e1->zs[warp_row + g    ][8 * j + 2 * t    ] = acc[j][0] * invA;
            e1->zs[warp_row + g    ][8 * j + 2 * t + 1] = acc[j][1] * invA;
            e1->zs[warp_row + g + 8][8 * j + 2 * t    ] = acc[j][2] * invB;
            e1->zs[warp_row + g + 8][8 * j + 2 * t + 1] = acc[j][3] * invB;
        }
        __syncthreads();
        float* dst = zout + ((size_t)b * NN + rowbase + lrow) * KK + lseg * 32;
        const float* src = &e1->zs[lrow][lseg * 32];
#pragma unroll
        for (int q = 0; q < 8; q++) ((float4*)dst)[q] = ((const float4*)src)[q];
        return;
    }

    // EPI == 0: stage z^T split bf16
#pragma unroll
    for (int j = 0; j < 8; j++) {
        __nv_bfloat16 hi, lo;
        split_bf16(acc[j][0] * invA, hi, lo);
        e0->zh[8 * j + 2 * t    ][warp_row + g    ] = hi; e0->zl[8 * j + 2 * t    ][warp_row + g    ] = lo;
        split_bf16(acc[j][1] * invA, hi, lo);
        e0->zh[8 * j + 2 * t + 1][warp_row + g    ] = hi; e0->zl[8 * j + 2 * t + 1][warp_row + g    ] = lo;
        split_bf16(acc[j][2] * invB, hi, lo);
        e0->zh[8 * j + 2 * t    ][warp_row + g + 8] = hi; e0->zl[8 * j + 2 * t    ][warp_row + g + 8] = lo;
        split_bf16(acc[j][3] * invB, hi, lo);
        e0->zh[8 * j + 2 * t + 1][warp_row + g + 8] = hi; e0->zl[8 * j + 2 * t + 1][warp_row + g + 8] = lo;
    }
    __syncthreads();
    {   // coalesced z^T global write: 64 k-rows x 128 n
        const int k = tid >> 2, q = tid & 3;
        __nv_bfloat16* dh = g_zthi + ((size_t)(b * KK + k)) * NN + rowbase + q * 32;
        __nv_bfloat16* dl = g_ztlo + ((size_t)(b * KK + k)) * NN + rowbase + q * 32;
        const __nv_bfloat16* sh = &e0->zh[k][q * 32];
        const __nv_bfloat16* sl = &e0->zl[k][q * 32];
#pragma unroll
        for (int r = 0; r < 4; r++) {
            ((uint4*)dh)[r] = ((const uint4*)sh)[r];
            ((uint4*)dl)[r] = ((const uint4*)sl)[r];
        }
    }
    if (tid < 64) {  // deterministic column sums over this n-block
        float s = 0.0f;
#pragma unroll 8
        for (int n = 0; n < 128; n++)
            s += __bfloat162float(e0->zh[tid][n]) + __bfloat162float(e0->zl[tid][n]);
        g_Spart[(blockIdx.x * BB + b) * KK + tid] = s;
    }
}

// -------- small reductions --------
__global__ void k_sumS() {
    int b = blockIdx.x, k = threadIdx.x;
    float s = 0.0f;
    for (int r = 0; r < NBLK1; r++) s += g_Spart[(r * BB + b) * KK + k];
    g_S[b * KK + k] = s;
}
__global__ void k_reduceScale() {
    int c = blockIdx.x, b = blockIdx.y, k = threadIdx.x;
    float s = 0.0f;
    size_t base = (((size_t)(b * NSPLIT)) * CC + c) * KK + k;
#pragma unroll 4
    for (int sp = 0; sp < NSPLIT; sp++) s += g_part[base + (size_t)sp * CC * KK];
    g_mtmp[(b * CC + c) * KK + k] = s / (EPSF + g_S[b * KK + k]);
}
__global__ void k_l2norm() {
    int k = blockIdx.x, b = blockIdx.y, c = threadIdx.x;   // 256 threads
    float v = g_mtmp[(b * CC + c) * KK + k];
    float sq = v * v;
#pragma unroll
    for (int m = 16; m; m >>= 1) sq += __shfl_xor_sync(0xffffffffu, sq, m);
    __shared__ float red[8];
    if ((threadIdx.x & 31) == 0) red[threadIdx.x >> 5] = sq;
    __syncthreads();
    float total = 0.0f;
#pragma unroll
    for (int w = 0; w < 8; w++) total += red[w];
    float out = v / (EPSF + sqrtf(total));
    __nv_bfloat16 hi, lo; split_bf16(out, hi, lo);
    size_t o = ((size_t)b * KK + k) * CC + c;
    g_mthi[o] = hi; g_mtlo[o] = lo;
}

// -------- launch --------
extern "C" void kernel_launch(void* const* d_in, const int* in_sizes, int n_in,
                              void* d_out, int out_size) {
    const float* x  = (const float*)d_in[0];
    const float* mu = (const float*)d_in[1];
    if (n_in >= 2 && in_sizes[0] < in_sizes[1]) { const float* tp = x; x = mu; mu = tp; }
    float* z = (float*)d_out;

    static int smem_set = 0;
    if (!smem_set) {
        cudaFuncSetAttribute(k_mma<0>, cudaFuncAttributeMaxDynamicSharedMemorySize, SMEM_MAIN);
        cudaFuncSetAttribute(k_mma<1>, cudaFuncAttributeMaxDynamicSharedMemorySize, SMEM_MAIN);
        cudaFuncSetAttribute(k_mma<2>, cudaFuncAttributeMaxDynamicSharedMemorySize, SMEM_MAIN);
        smem_set = 1;
    }

    k_prep<<<dim3(NN / 32, CC / 32, BB), dim3(32, 8)>>>(x);
    k_initm<<<(BB * KK * CC) / 256, 256>>>(mu);

    for (int s = 0; s < EM_STEPS; s++) {
        k_mma<0><<<dim3(NBLK1, BB), 256, SMEM_MAIN>>>(nullptr);
        k_mma<2><<<dim3(CC / 128, NSPLIT, BB), 256, SMEM_MAIN>>>(nullptr);
        k_sumS<<<BB, KK>>>();
        k_reduceScale<<<dim3(CC, BB), KK>>>();
        k_l2norm<<<dim3(KK, BB), 256>>>();
    }
    // final soft assignment: NO temperature in the reference here
    k_mma<1><<<dim3(NBLK1, BB), 256, SMEM_MAIN>>>(z);
}